// round 1
// baseline (speedup 1.0000x reference)
#include <cuda_runtime.h>
#include <math.h>

#define BATCH 4
#define SEQ   2048
#define DMODEL 1024
#define DK    64

// scratch: projected q, k, v  (BATCH*SEQ*DK floats = 2 MB each)
__device__ float g_q[BATCH * SEQ * DK];
__device__ float g_k[BATCH * SEQ * DK];
__device__ float g_v[BATCH * SEQ * DK];

// ---------------------------------------------------------------------------
// Projection: out[r][c] = sum_d X[r][d] * W[d][c] + bias[c]
// X: [8192, 1024], W: [1024, 64], out: [8192, 64]
// CTA: 256 threads, computes a 64-row x 64-col output tile.
// Thread (tx = tid&15, ty = tid>>4) owns rows ty*4+i, cols tx + j*16 (4x4).
// ---------------------------------------------------------------------------
template <int WHICH>
__global__ __launch_bounds__(256) void proj_kernel(
    const float* __restrict__ X,
    const float* __restrict__ W,
    const float* __restrict__ bias)
{
    float* out = (WHICH == 0) ? g_q : (WHICH == 1) ? g_k : g_v;

    __shared__ float Xs[64][33];   // padded: conflict-free column reads
    __shared__ float Ws[32][65];

    const int tid = threadIdx.x;
    const int tx = tid & 15;
    const int ty = tid >> 4;
    const int row0 = blockIdx.x * 64;

    float acc[4][4] = {};

    for (int k0 = 0; k0 < DMODEL; k0 += 32) {
        // load X tile: 64 rows x 32 cols (2048 elems, 8 per thread, coalesced)
        #pragma unroll
        for (int it = 0; it < 8; it++) {
            int idx = tid + it * 256;
            int r = idx >> 5, kk = idx & 31;
            Xs[r][kk] = X[(size_t)(row0 + r) * DMODEL + k0 + kk];
        }
        // load W tile: 32 rows x 64 cols (coalesced)
        #pragma unroll
        for (int it = 0; it < 8; it++) {
            int idx = tid + it * 256;
            int kk = idx >> 6, c = idx & 63;
            Ws[kk][c] = W[(size_t)(k0 + kk) * DK + c];
        }
        __syncthreads();

        #pragma unroll 8
        for (int kk = 0; kk < 32; kk++) {
            float a[4], b[4];
            #pragma unroll
            for (int i = 0; i < 4; i++) a[i] = Xs[ty * 4 + i][kk];
            #pragma unroll
            for (int j = 0; j < 4; j++) b[j] = Ws[kk][tx + j * 16];
            #pragma unroll
            for (int i = 0; i < 4; i++)
                #pragma unroll
                for (int j = 0; j < 4; j++)
                    acc[i][j] = fmaf(a[i], b[j], acc[i][j]);
        }
        __syncthreads();
    }

    #pragma unroll
    for (int i = 0; i < 4; i++) {
        int r = row0 + ty * 4 + i;
        #pragma unroll
        for (int j = 0; j < 4; j++) {
            int c = tx + j * 16;
            out[(size_t)r * DK + c] = acc[i][j] + bias[c];
        }
    }
}

// ---------------------------------------------------------------------------
// Flash attention: one CTA per (batch, 64-query tile).
// Online softmax; 16-lane groups (same ty) own a query row across 64 key cols.
// Dynamic smem: Qs/Ks/Vs/Ps each [64][65] floats = 66560 bytes total.
// ---------------------------------------------------------------------------
extern __shared__ float sm_attn[];

__global__ __launch_bounds__(256) void attn_kernel(float* __restrict__ out)
{
    const int b  = blockIdx.y;
    const int q0 = blockIdx.x * 64;

    float* Qs = sm_attn;            // [64][65]
    float* Ks = Qs + 64 * 65;
    float* Vs = Ks + 64 * 65;
    float* Ps = Vs + 64 * 65;

    const int tid = threadIdx.x;
    const int tx = tid & 15;
    const int ty = tid >> 4;

    const float* qptr = g_q + (size_t)b * SEQ * DK;
    const float* kptr = g_k + (size_t)b * SEQ * DK;
    const float* vptr = g_v + (size_t)b * SEQ * DK;

    // load Q tile (4096 elems, 16 per thread, coalesced)
    #pragma unroll
    for (int it = 0; it < 16; it++) {
        int idx = tid + it * 256;
        int r = idx >> 6, c = idx & 63;
        Qs[r * 65 + c] = qptr[(size_t)(q0 + r) * DK + c];
    }

    float m[4], l[4], o[4][4];
    #pragma unroll
    for (int i = 0; i < 4; i++) {
        m[i] = -1e30f;
        l[i] = 0.0f;
        #pragma unroll
        for (int j = 0; j < 4; j++) o[i][j] = 0.0f;
    }

    const float scale = 0.125f;  // 1/sqrt(64)

    for (int kb = 0; kb < SEQ / 64; kb++) {
        __syncthreads();  // prior-iter reads done (covers Q-load on iter 0)

        // load K, V tiles (coalesced)
        #pragma unroll
        for (int it = 0; it < 16; it++) {
            int idx = tid + it * 256;
            int r = idx >> 6, c = idx & 63;
            Ks[r * 65 + c] = kptr[(size_t)(kb * 64 + r) * DK + c];
            Vs[r * 65 + c] = vptr[(size_t)(kb * 64 + r) * DK + c];
        }
        __syncthreads();

        // S = Q K^T : thread owns rows ty*4+i, key-cols tx + j*16
        float s[4][4] = {};
        #pragma unroll 16
        for (int kk = 0; kk < DK; kk++) {
            float a[4], bb[4];
            #pragma unroll
            for (int i = 0; i < 4; i++) a[i] = Qs[(ty * 4 + i) * 65 + kk];
            #pragma unroll
            for (int j = 0; j < 4; j++) bb[j] = Ks[(tx + j * 16) * 65 + kk];
            #pragma unroll
            for (int i = 0; i < 4; i++)
                #pragma unroll
                for (int j = 0; j < 4; j++)
                    s[i][j] = fmaf(a[i], bb[j], s[i][j]);
        }

        // online softmax per query row (reduce across the 16 tx lanes)
        #pragma unroll
        for (int i = 0; i < 4; i++) {
            float s0 = s[i][0] * scale, s1 = s[i][1] * scale;
            float s2 = s[i][2] * scale, s3 = s[i][3] * scale;
            float mloc = fmaxf(fmaxf(s0, s1), fmaxf(s2, s3));
            #pragma unroll
            for (int off = 8; off >= 1; off >>= 1)
                mloc = fmaxf(mloc, __shfl_xor_sync(0xffffffffu, mloc, off));
            float mnew = fmaxf(m[i], mloc);
            float corr = __expf(m[i] - mnew);
            float p0 = __expf(s0 - mnew);
            float p1 = __expf(s1 - mnew);
            float p2 = __expf(s2 - mnew);
            float p3 = __expf(s3 - mnew);
            int prow = (ty * 4 + i) * 65 + tx;
            Ps[prow +  0] = p0;
            Ps[prow + 16] = p1;
            Ps[prow + 32] = p2;
            Ps[prow + 48] = p3;
            float psum = p0 + p1 + p2 + p3;
            #pragma unroll
            for (int off = 8; off >= 1; off >>= 1)
                psum += __shfl_xor_sync(0xffffffffu, psum, off);
            l[i] = l[i] * corr + psum;
            m[i] = mnew;
            #pragma unroll
            for (int j = 0; j < 4; j++) o[i][j] *= corr;
        }
        __syncthreads();  // Ps visible

        // O += P V : thread owns rows ty*4+i, v-cols tx + j*16
        #pragma unroll 16
        for (int kk = 0; kk < 64; kk++) {
            float a[4], bb[4];
            #pragma unroll
            for (int i = 0; i < 4; i++) a[i] = Ps[(ty * 4 + i) * 65 + kk];
            #pragma unroll
            for (int j = 0; j < 4; j++) bb[j] = Vs[kk * 65 + tx + j * 16];
            #pragma unroll
            for (int i = 0; i < 4; i++)
                #pragma unroll
                for (int j = 0; j < 4; j++)
                    o[i][j] = fmaf(a[i], bb[j], o[i][j]);
        }
    }

    // final normalize + store
    #pragma unroll
    for (int i = 0; i < 4; i++) {
        float inv = 1.0f / l[i];
        size_t row = (size_t)b * SEQ + q0 + ty * 4 + i;
        #pragma unroll
        for (int j = 0; j < 4; j++)
            out[row * DK + tx + j * 16] = o[i][j] * inv;
    }
}

// ---------------------------------------------------------------------------
// Launch
// inputs: 0=query 1=key 2=value 3=Wq 4=bq 5=Wk 6=bk 7=Wv 8=bv
// ---------------------------------------------------------------------------
extern "C" void kernel_launch(void* const* d_in, const int* in_sizes, int n_in,
                              void* d_out, int out_size)
{
    const float* query = (const float*)d_in[0];
    const float* key   = (const float*)d_in[1];
    const float* value = (const float*)d_in[2];
    const float* Wq    = (const float*)d_in[3];
    const float* bq    = (const float*)d_in[4];
    const float* Wk    = (const float*)d_in[5];
    const float* bk    = (const float*)d_in[6];
    const float* Wv    = (const float*)d_in[7];
    const float* bv    = (const float*)d_in[8];
    float* out = (float*)d_out;

    const int rows = BATCH * SEQ;           // 8192
    dim3 pgrid(rows / 64);                   // 128
    proj_kernel<0><<<pgrid, 256>>>(query, Wq, bq);
    proj_kernel<1><<<pgrid, 256>>>(key,   Wk, bk);
    proj_kernel<2><<<pgrid, 256>>>(value, Wv, bv);

    const int smem = 4 * 64 * 65 * (int)sizeof(float);  // 66560 B
    static bool attr_set = false;
    if (!attr_set) {
        cudaFuncSetAttribute(attn_kernel,
                             cudaFuncAttributeMaxDynamicSharedMemorySize, smem);
        attr_set = true;
    }
    dim3 agrid(SEQ / 64, BATCH);             // (32, 4)
    attn_kernel<<<agrid, 256, smem>>>(out);
}

// round 3
// speedup vs baseline: 1.6991x; 1.6991x over previous
#include <cuda_runtime.h>
#include <cuda_bf16.h>
#include <cstdint>
#include <math.h>

#define BATCH  4
#define SEQ    2048
#define DMODEL 1024
#define DK     64

// scratch: projected q, k, v (fp32)
__device__ float g_q[BATCH * SEQ * DK];
__device__ float g_k[BATCH * SEQ * DK];
__device__ float g_v[BATCH * SEQ * DK];
// pre-transposed + bf16-split weights: [matrix][n][k]  (n=0..63, k=0..1023)
__device__ __align__(16) __nv_bfloat16 g_wt_hi[3 * DK * DMODEL];
__device__ __align__(16) __nv_bfloat16 g_wt_lo[3 * DK * DMODEL];

// ============================ mma.sync helper ============================
// D[16x8] += A[16x16] * B[16x8] : row.col, bf16 in, fp32 accum
__device__ __forceinline__ void mma16816(float c[4], const uint32_t a[4],
                                         const uint32_t b[2]) {
    asm volatile(
        "mma.sync.aligned.m16n8k16.row.col.f32.bf16.bf16.f32 "
        "{%0, %1, %2, %3}, {%4, %5, %6, %7}, {%8, %9}, {%0, %1, %2, %3};"
        : "+f"(c[0]), "+f"(c[1]), "+f"(c[2]), "+f"(c[3])
        : "r"(a[0]), "r"(a[1]), "r"(a[2]), "r"(a[3]), "r"(b[0]), "r"(b[1]));
}

__device__ __forceinline__ void split2(float a, float b, uint32_t& hi, uint32_t& lo) {
    __nv_bfloat16 ha = __float2bfloat16_rn(a);
    __nv_bfloat16 hb = __float2bfloat16_rn(b);
    __nv_bfloat16 la = __float2bfloat16_rn(a - __bfloat162float(ha));
    __nv_bfloat16 lb = __float2bfloat16_rn(b - __bfloat162float(hb));
    __nv_bfloat162 h2; h2.x = ha; h2.y = hb;
    __nv_bfloat162 l2; l2.x = la; l2.y = lb;
    hi = *reinterpret_cast<uint32_t*>(&h2);
    lo = *reinterpret_cast<uint32_t*>(&l2);
}

// ============================ prep: transpose + split weights ============================
__global__ __launch_bounds__(256) void prep_w(const float* __restrict__ Wq,
                                              const float* __restrict__ Wk,
                                              const float* __restrict__ Wv)
{
    const int m = blockIdx.x;
    const float* W = (m == 0) ? Wq : (m == 1) ? Wk : Wv;   // [1024, 64] row-major
    __nv_bfloat16* th = g_wt_hi + m * DK * DMODEL;
    __nv_bfloat16* tl = g_wt_lo + m * DK * DMODEL;
    #pragma unroll
    for (int it = 0; it < 32; it++) {
        int gi = blockIdx.y * 8192 + threadIdx.x + it * 256;  // over 65536 elems
        int k = gi >> 6, n = gi & 63;
        float w = W[gi];
        __nv_bfloat16 h = __float2bfloat16_rn(w);
        float r = w - __bfloat162float(h);
        th[n * DMODEL + k] = h;
        tl[n * DMODEL + k] = __float2bfloat16_rn(r);
    }
}

// ============================ mma.sync projection ============================
// grid (64, 3): blockIdx.x = 128-row tile, blockIdx.y = which matrix.
// D[128,64] = X[128,1024] * W[1024,64] + bias, split-bf16 (3 MMA terms).
// smem (bf16 elems): Xh[128][72], Xl[128][72], Wh[64][80], Wl[64][80]
#define XSTR 72
#define WSTR 80
static const int PS_XH = 0;
static const int PS_XL = 128 * XSTR;              // 9216 elems
static const int PS_WH = 2 * 128 * XSTR;          // 18432
static const int PS_WL = 2 * 128 * XSTR + 64 * WSTR;
static const int PS_ELEMS = 2 * 128 * XSTR + 2 * 64 * WSTR;   // 28672 elems = 57344 B

__device__ __forceinline__ void proj_ldg(const float* __restrict__ X, int row0, int c,
                                         int tid,
                                         const __nv_bfloat16* __restrict__ wh,
                                         const __nv_bfloat16* __restrict__ wl,
                                         float4 xr[8], uint4 wrh[2], uint4 wrl[2])
{
    #pragma unroll
    for (int it = 0; it < 8; it++) {
        int idx = tid + it * 256;
        int r = idx >> 4, c4 = idx & 15;
        xr[it] = *(const float4*)(X + (size_t)(row0 + r) * DMODEL + c * 64 + c4 * 4);
    }
    #pragma unroll
    for (int it = 0; it < 2; it++) {
        int idx = tid + it * 256;
        int n = idx >> 3, c8 = idx & 7;
        wrh[it] = *(const uint4*)(wh + n * DMODEL + c * 64 + c8 * 8);
        wrl[it] = *(const uint4*)(wl + n * DMODEL + c * 64 + c8 * 8);
    }
}

__global__ __launch_bounds__(256) void proj_mma(
    const float* __restrict__ Xq, const float* __restrict__ Xk,
    const float* __restrict__ Xv,
    const float* __restrict__ bq, const float* __restrict__ bk,
    const float* __restrict__ bv)
{
    extern __shared__ __nv_bfloat16 sm[];
    __nv_bfloat16* Xh = sm + PS_XH;
    __nv_bfloat16* Xl = sm + PS_XL;
    __nv_bfloat16* Wh = sm + PS_WH;
    __nv_bfloat16* Wl = sm + PS_WL;

    const int tid = threadIdx.x;
    const int wid = tid >> 5;
    const int lane = tid & 31;
    const int g  = lane >> 2;   // group 0-7
    const int tg = lane & 3;    // thread-in-group
    const int m = blockIdx.y;
    const int row0 = blockIdx.x * 128;

    const float* X    = (m == 0) ? Xq : (m == 1) ? Xk : Xv;
    const float* bias = (m == 0) ? bq : (m == 1) ? bk : bv;
    float* out        = (m == 0) ? g_q : (m == 1) ? g_k : g_v;
    const __nv_bfloat16* wh = g_wt_hi + m * DK * DMODEL;
    const __nv_bfloat16* wl = g_wt_lo + m * DK * DMODEL;

    float acc[8][4];    // 8 n-tiles (n = j*8..j*8+7), c-fragment each
    #pragma unroll
    for (int j = 0; j < 8; j++)
        #pragma unroll
        for (int q = 0; q < 4; q++) acc[j][q] = 0.0f;

    float4 xr[8]; uint4 wrh[2], wrl[2];
    proj_ldg(X, row0, 0, tid, wh, wl, xr, wrh, wrl);

    const int wrow = wid * 16;   // this warp's 16-row slab

    for (int c = 0; c < 16; c++) {
        if (c > 0) __syncthreads();   // previous iter's smem reads complete

        // store X chunk (fp32 -> bf16 hi/lo), rows [0,128) x k [0,64)
        #pragma unroll
        for (int it = 0; it < 8; it++) {
            int idx = tid + it * 256;
            int r = idx >> 4, c4 = idx & 15;
            uint32_t h0, l0, h1, l1;
            split2(xr[it].x, xr[it].y, h0, l0);
            split2(xr[it].z, xr[it].w, h1, l1);
            *(uint2*)&Xh[r * XSTR + c4 * 4] = make_uint2(h0, h1);
            *(uint2*)&Xl[r * XSTR + c4 * 4] = make_uint2(l0, l1);
        }
        // store W chunk (bf16 already), n [0,64) x k [0,64)
        #pragma unroll
        for (int it = 0; it < 2; it++) {
            int idx = tid + it * 256;
            int n = idx >> 3, c8 = idx & 7;
            *(uint4*)&Wh[n * WSTR + c8 * 8] = wrh[it];
            *(uint4*)&Wl[n * WSTR + c8 * 8] = wrl[it];
        }
        __syncthreads();

        if (c < 15)
            proj_ldg(X, row0, c + 1, tid, wh, wl, xr, wrh, wrl);

        // 4 k-steps of 16 within the 64-wide chunk
        #pragma unroll
        for (int ks = 0; ks < 4; ks++) {
            const int k0 = ks * 16;
            uint32_t ah[4], al[4];
            ah[0] = *(const uint32_t*)&Xh[(wrow + g    ) * XSTR + k0 + tg * 2];
            ah[1] = *(const uint32_t*)&Xh[(wrow + g + 8) * XSTR + k0 + tg * 2];
            ah[2] = *(const uint32_t*)&Xh[(wrow + g    ) * XSTR + k0 + 8 + tg * 2];
            ah[3] = *(const uint32_t*)&Xh[(wrow + g + 8) * XSTR + k0 + 8 + tg * 2];
            al[0] = *(const uint32_t*)&Xl[(wrow + g    ) * XSTR + k0 + tg * 2];
            al[1] = *(const uint32_t*)&Xl[(wrow + g + 8) * XSTR + k0 + tg * 2];
            al[2] = *(const uint32_t*)&Xl[(wrow + g    ) * XSTR + k0 + 8 + tg * 2];
            al[3] = *(const uint32_t*)&Xl[(wrow + g + 8) * XSTR + k0 + 8 + tg * 2];
            #pragma unroll
            for (int j = 0; j < 8; j++) {
                const int n = j * 8 + g;
                uint32_t bh[2], bl[2];
                bh[0] = *(const uint32_t*)&Wh[n * WSTR + k0 + tg * 2];
                bh[1] = *(const uint32_t*)&Wh[n * WSTR + k0 + 8 + tg * 2];
                bl[0] = *(const uint32_t*)&Wl[n * WSTR + k0 + tg * 2];
                bl[1] = *(const uint32_t*)&Wl[n * WSTR + k0 + 8 + tg * 2];
                mma16816(acc[j], ah, bh);   // hi * hi
                mma16816(acc[j], ah, bl);   // hi * lo
                mma16816(acc[j], al, bh);   // lo * hi
            }
        }
    }

    // epilogue: c0,c1 -> row wrow+g, cols j*8+tg*2 (+1); c2,c3 -> row wrow+g+8
    #pragma unroll
    for (int j = 0; j < 8; j++) {
        const int col = j * 8 + tg * 2;
        const float b0 = __ldg(bias + col);
        const float b1 = __ldg(bias + col + 1);
        size_t r0 = (size_t)(row0 + wrow + g) * DK + col;
        size_t r1 = (size_t)(row0 + wrow + g + 8) * DK + col;
        *(float2*)(out + r0) = make_float2(acc[j][0] + b0, acc[j][1] + b1);
        *(float2*)(out + r1) = make_float2(acc[j][2] + b0, acc[j][3] + b1);
    }
}

// ============================ flash attention (SIMT, fp32) ============================
// 32-query tiles, 128 threads, grid (64, 4) = 256 CTAs -> 2 CTAs/SM.
// smem: Qs[32][68] Ks[64][68] Vs[64][68] Ps[32][68] = 52224 B
__global__ __launch_bounds__(128) void attn_kernel(float* __restrict__ out)
{
    extern __shared__ float smf[];
    float* Qs = smf;
    float* Ks = Qs + 32 * 68;
    float* Vs = Ks + 64 * 68;
    float* Ps = Vs + 64 * 68;

    const int b  = blockIdx.y;
    const int q0 = blockIdx.x * 32;
    const int tid = threadIdx.x;
    const int tx = tid & 15;
    const int ty = tid >> 4;

    const float* qptr = g_q + (size_t)b * SEQ * DK;
    const float* kptr = g_k + (size_t)b * SEQ * DK;
    const float* vptr = g_v + (size_t)b * SEQ * DK;

    #pragma unroll
    for (int it = 0; it < 4; it++) {
        int idx = tid + it * 128;
        int r = idx >> 4, c4 = idx & 15;
        *(float4*)&Qs[r * 68 + c4 * 4] =
            *(const float4*)(qptr + (size_t)(q0 + r) * DK + c4 * 4);
    }

    float m[4], l[4], o[4][4];
    #pragma unroll
    for (int i = 0; i < 4; i++) {
        m[i] = -1e30f; l[i] = 0.0f;
        #pragma unroll
        for (int j = 0; j < 4; j++) o[i][j] = 0.0f;
    }
    const float scale = 0.125f;

    for (int kb = 0; kb < SEQ / 64; kb++) {
        __syncthreads();

        #pragma unroll
        for (int it = 0; it < 8; it++) {
            int idx = tid + it * 128;
            int r = idx >> 4, c4 = idx & 15;
            *(float4*)&Ks[r * 68 + c4 * 4] =
                *(const float4*)(kptr + (size_t)(kb * 64 + r) * DK + c4 * 4);
            *(float4*)&Vs[r * 68 + c4 * 4] =
                *(const float4*)(vptr + (size_t)(kb * 64 + r) * DK + c4 * 4);
        }
        __syncthreads();

        // S = Q K^T
        float s[4][4] = {};
        #pragma unroll 4
        for (int k4 = 0; k4 < 16; k4++) {
            const int kk = k4 * 4;
            float4 a4[4], b4[4];
            #pragma unroll
            for (int i = 0; i < 4; i++) a4[i] = *(const float4*)&Qs[(ty * 4 + i) * 68 + kk];
            #pragma unroll
            for (int j = 0; j < 4; j++) b4[j] = *(const float4*)&Ks[(tx + j * 16) * 68 + kk];
            #pragma unroll
            for (int i = 0; i < 4; i++)
                #pragma unroll
                for (int j = 0; j < 4; j++) {
                    s[i][j] = fmaf(a4[i].x, b4[j].x, s[i][j]);
                    s[i][j] = fmaf(a4[i].y, b4[j].y, s[i][j]);
                    s[i][j] = fmaf(a4[i].z, b4[j].z, s[i][j]);
                    s[i][j] = fmaf(a4[i].w, b4[j].w, s[i][j]);
                }
        }

        // online softmax (reduce across 16 tx lanes)
        #pragma unroll
        for (int i = 0; i < 4; i++) {
            float s0 = s[i][0] * scale, s1 = s[i][1] * scale;
            float s2 = s[i][2] * scale, s3 = s[i][3] * scale;
            float mloc = fmaxf(fmaxf(s0, s1), fmaxf(s2, s3));
            #pragma unroll
            for (int off = 8; off >= 1; off >>= 1)
                mloc = fmaxf(mloc, __shfl_xor_sync(0xffffffffu, mloc, off));
            float mnew = fmaxf(m[i], mloc);
            float corr = __expf(m[i] - mnew);
            float p0 = __expf(s0 - mnew);
            float p1 = __expf(s1 - mnew);
            float p2 = __expf(s2 - mnew);
            float p3 = __expf(s3 - mnew);
            int prow = (ty * 4 + i) * 68 + tx;
            Ps[prow +  0] = p0;
            Ps[prow + 16] = p1;
            Ps[prow + 32] = p2;
            Ps[prow + 48] = p3;
            float psum = p0 + p1 + p2 + p3;
            #pragma unroll
            for (int off = 8; off >= 1; off >>= 1)
                psum += __shfl_xor_sync(0xffffffffu, psum, off);
            l[i] = l[i] * corr + psum;
            m[i] = mnew;
            #pragma unroll
            for (int j = 0; j < 4; j++) o[i][j] *= corr;
        }
        __syncthreads();

        // O += P V
        #pragma unroll 4
        for (int k4 = 0; k4 < 16; k4++) {
            const int kk = k4 * 4;
            float4 a4[4];
            #pragma unroll
            for (int i = 0; i < 4; i++) a4[i] = *(const float4*)&Ps[(ty * 4 + i) * 68 + kk];
            float bb[4][4];
            #pragma unroll
            for (int q = 0; q < 4; q++)
                #pragma unroll
                for (int j = 0; j < 4; j++)
                    bb[q][j] = Vs[(kk + q) * 68 + tx + j * 16];
            #pragma unroll
            for (int i = 0; i < 4; i++)
                #pragma unroll
                for (int j = 0; j < 4; j++) {
                    o[i][j] = fmaf(a4[i].x, bb[0][j], o[i][j]);
                    o[i][j] = fmaf(a4[i].y, bb[1][j], o[i][j]);
                    o[i][j] = fmaf(a4[i].z, bb[2][j], o[i][j]);
                    o[i][j] = fmaf(a4[i].w, bb[3][j], o[i][j]);
                }
        }
    }

    #pragma unroll
    for (int i = 0; i < 4; i++) {
        float inv = 1.0f / l[i];
        size_t row = (size_t)b * SEQ + q0 + ty * 4 + i;
        #pragma unroll
        for (int j = 0; j < 4; j++)
            out[row * DK + tx + j * 16] = o[i][j] * inv;
    }
}

// ============================ launch ============================
extern "C" void kernel_launch(void* const* d_in, const int* in_sizes, int n_in,
                              void* d_out, int out_size)
{
    const float* query = (const float*)d_in[0];
    const float* key   = (const float*)d_in[1];
    const float* value = (const float*)d_in[2];
    const float* Wq    = (const float*)d_in[3];
    const float* bq    = (const float*)d_in[4];
    const float* Wk    = (const float*)d_in[5];
    const float* bk    = (const float*)d_in[6];
    const float* Wv    = (const float*)d_in[7];
    const float* bv    = (const float*)d_in[8];
    float* out = (float*)d_out;

    const int proj_smem = PS_ELEMS * (int)sizeof(__nv_bfloat16);  // 57344
    const int attn_smem = 192 * 68 * (int)sizeof(float);          // 52224
    static bool attr_set = false;
    if (!attr_set) {
        cudaFuncSetAttribute(proj_mma,
                             cudaFuncAttributeMaxDynamicSharedMemorySize, proj_smem);
        cudaFuncSetAttribute(attn_kernel,
                             cudaFuncAttributeMaxDynamicSharedMemorySize, attn_smem);
        attr_set = true;
    }

    prep_w<<<dim3(3, 8), 256>>>(Wq, Wk, Wv);
    proj_mma<<<dim3(64, 3), 256, proj_smem>>>(query, key, value, bq, bk, bv);
    attn_kernel<<<dim3(SEQ / 32, BATCH), 128, attn_smem>>>(out);
}

// round 4
// speedup vs baseline: 2.3775x; 1.3993x over previous
#include <cuda_runtime.h>
#include <cuda_bf16.h>
#include <cstdint>
#include <math.h>

#define BATCH  4
#define SEQ    2048
#define DMODEL 1024
#define DK     64

// projected activations, split bf16
__device__ __align__(16) __nv_bfloat16 g_qh[BATCH * SEQ * DK];
__device__ __align__(16) __nv_bfloat16 g_ql[BATCH * SEQ * DK];
__device__ __align__(16) __nv_bfloat16 g_kh[BATCH * SEQ * DK];
__device__ __align__(16) __nv_bfloat16 g_kl[BATCH * SEQ * DK];
// V transposed: [batch][vcol][seq]
__device__ __align__(16) __nv_bfloat16 g_vth[BATCH * DK * SEQ];
__device__ __align__(16) __nv_bfloat16 g_vtl[BATCH * DK * SEQ];
// pre-transposed + bf16-split weights: [matrix][n][k]
__device__ __align__(16) __nv_bfloat16 g_wt_hi[3 * DK * DMODEL];
__device__ __align__(16) __nv_bfloat16 g_wt_lo[3 * DK * DMODEL];

// ============================ mma.sync helper ============================
__device__ __forceinline__ void mma16816(float c[4], const uint32_t a[4],
                                         const uint32_t b[2]) {
    asm volatile(
        "mma.sync.aligned.m16n8k16.row.col.f32.bf16.bf16.f32 "
        "{%0, %1, %2, %3}, {%4, %5, %6, %7}, {%8, %9}, {%0, %1, %2, %3};"
        : "+f"(c[0]), "+f"(c[1]), "+f"(c[2]), "+f"(c[3])
        : "r"(a[0]), "r"(a[1]), "r"(a[2]), "r"(a[3]), "r"(b[0]), "r"(b[1]));
}

__device__ __forceinline__ void split2(float a, float b, uint32_t& hi, uint32_t& lo) {
    __nv_bfloat16 ha = __float2bfloat16_rn(a);
    __nv_bfloat16 hb = __float2bfloat16_rn(b);
    __nv_bfloat16 la = __float2bfloat16_rn(a - __bfloat162float(ha));
    __nv_bfloat16 lb = __float2bfloat16_rn(b - __bfloat162float(hb));
    __nv_bfloat162 h2; h2.x = ha; h2.y = hb;
    __nv_bfloat162 l2; l2.x = la; l2.y = lb;
    hi = *reinterpret_cast<uint32_t*>(&h2);
    lo = *reinterpret_cast<uint32_t*>(&l2);
}

// ============================ prep: transpose + split weights ============================
// grid (3, 64): big enough to not be latency-bound.
__global__ __launch_bounds__(256) void prep_w(const float* __restrict__ Wq,
                                              const float* __restrict__ Wk,
                                              const float* __restrict__ Wv)
{
    const int m = blockIdx.x;
    const float* W = (m == 0) ? Wq : (m == 1) ? Wk : Wv;   // [1024, 64] row-major
    __nv_bfloat16* th = g_wt_hi + m * DK * DMODEL;
    __nv_bfloat16* tl = g_wt_lo + m * DK * DMODEL;
    int gi4 = (blockIdx.y * 256 + threadIdx.x) * 4;
    float4 w4 = *(const float4*)(W + gi4);
    const float wv[4] = {w4.x, w4.y, w4.z, w4.w};
    #pragma unroll
    for (int e = 0; e < 4; e++) {
        int gi = gi4 + e;
        int k = gi >> 6, n = gi & 63;
        __nv_bfloat16 h = __float2bfloat16_rn(wv[e]);
        float r = wv[e] - __bfloat162float(h);
        th[n * DMODEL + k] = h;
        tl[n * DMODEL + k] = __float2bfloat16_rn(r);
    }
}

// ============================ mma.sync projection ============================
#define XSTR 72
#define WSTR 80
static const int PS_XH = 0;
static const int PS_XL = 128 * XSTR;
static const int PS_WH = 2 * 128 * XSTR;
static const int PS_WL = 2 * 128 * XSTR + 64 * WSTR;
static const int PS_ELEMS = 2 * 128 * XSTR + 2 * 64 * WSTR;   // 28672 elems = 57344 B

__device__ __forceinline__ void proj_ldg(const float* __restrict__ X, int row0, int c,
                                         int tid,
                                         const __nv_bfloat16* __restrict__ wh,
                                         const __nv_bfloat16* __restrict__ wl,
                                         float4 xr[8], uint4 wrh[2], uint4 wrl[2])
{
    #pragma unroll
    for (int it = 0; it < 8; it++) {
        int idx = tid + it * 256;
        int r = idx >> 4, c4 = idx & 15;
        xr[it] = *(const float4*)(X + (size_t)(row0 + r) * DMODEL + c * 64 + c4 * 4);
    }
    #pragma unroll
    for (int it = 0; it < 2; it++) {
        int idx = tid + it * 256;
        int n = idx >> 3, c8 = idx & 7;
        wrh[it] = *(const uint4*)(wh + n * DMODEL + c * 64 + c8 * 8);
        wrl[it] = *(const uint4*)(wl + n * DMODEL + c * 64 + c8 * 8);
    }
}

__global__ __launch_bounds__(256) void proj_mma(
    const float* __restrict__ Xq, const float* __restrict__ Xk,
    const float* __restrict__ Xv,
    const float* __restrict__ bq, const float* __restrict__ bk,
    const float* __restrict__ bv)
{
    extern __shared__ __nv_bfloat16 sm[];
    __nv_bfloat16* Xh = sm + PS_XH;
    __nv_bfloat16* Xl = sm + PS_XL;
    __nv_bfloat16* Wh = sm + PS_WH;
    __nv_bfloat16* Wl = sm + PS_WL;

    const int tid = threadIdx.x;
    const int wid = tid >> 5;
    const int lane = tid & 31;
    const int g  = lane >> 2;
    const int tg = lane & 3;
    const int m = blockIdx.y;
    const int row0 = blockIdx.x * 128;

    const float* X    = (m == 0) ? Xq : (m == 1) ? Xk : Xv;
    const float* bias = (m == 0) ? bq : (m == 1) ? bk : bv;
    const __nv_bfloat16* wh = g_wt_hi + m * DK * DMODEL;
    const __nv_bfloat16* wl = g_wt_lo + m * DK * DMODEL;

    float acc[8][4];
    #pragma unroll
    for (int j = 0; j < 8; j++)
        #pragma unroll
        for (int q = 0; q < 4; q++) acc[j][q] = 0.0f;

    float4 xr[8]; uint4 wrh[2], wrl[2];
    proj_ldg(X, row0, 0, tid, wh, wl, xr, wrh, wrl);

    const int wrow = wid * 16;

    for (int c = 0; c < 16; c++) {
        if (c > 0) __syncthreads();

        #pragma unroll
        for (int it = 0; it < 8; it++) {
            int idx = tid + it * 256;
            int r = idx >> 4, c4 = idx & 15;
            uint32_t h0, l0, h1, l1;
            split2(xr[it].x, xr[it].y, h0, l0);
            split2(xr[it].z, xr[it].w, h1, l1);
            *(uint2*)&Xh[r * XSTR + c4 * 4] = make_uint2(h0, h1);
            *(uint2*)&Xl[r * XSTR + c4 * 4] = make_uint2(l0, l1);
        }
        #pragma unroll
        for (int it = 0; it < 2; it++) {
            int idx = tid + it * 256;
            int n = idx >> 3, c8 = idx & 7;
            *(uint4*)&Wh[n * WSTR + c8 * 8] = wrh[it];
            *(uint4*)&Wl[n * WSTR + c8 * 8] = wrl[it];
        }
        __syncthreads();

        if (c < 15)
            proj_ldg(X, row0, c + 1, tid, wh, wl, xr, wrh, wrl);

        #pragma unroll
        for (int ks = 0; ks < 4; ks++) {
            const int k0 = ks * 16;
            uint32_t ah[4], al[4];
            ah[0] = *(const uint32_t*)&Xh[(wrow + g    ) * XSTR + k0 + tg * 2];
            ah[1] = *(const uint32_t*)&Xh[(wrow + g + 8) * XSTR + k0 + tg * 2];
            ah[2] = *(const uint32_t*)&Xh[(wrow + g    ) * XSTR + k0 + 8 + tg * 2];
            ah[3] = *(const uint32_t*)&Xh[(wrow + g + 8) * XSTR + k0 + 8 + tg * 2];
            al[0] = *(const uint32_t*)&Xl[(wrow + g    ) * XSTR + k0 + tg * 2];
            al[1] = *(const uint32_t*)&Xl[(wrow + g + 8) * XSTR + k0 + tg * 2];
            al[2] = *(const uint32_t*)&Xl[(wrow + g    ) * XSTR + k0 + 8 + tg * 2];
            al[3] = *(const uint32_t*)&Xl[(wrow + g + 8) * XSTR + k0 + 8 + tg * 2];
            #pragma unroll
            for (int j = 0; j < 8; j++) {
                const int n = j * 8 + g;
                uint32_t bh[2], bl[2];
                bh[0] = *(const uint32_t*)&Wh[n * WSTR + k0 + tg * 2];
                bh[1] = *(const uint32_t*)&Wh[n * WSTR + k0 + 8 + tg * 2];
                bl[0] = *(const uint32_t*)&Wl[n * WSTR + k0 + tg * 2];
                bl[1] = *(const uint32_t*)&Wl[n * WSTR + k0 + 8 + tg * 2];
                mma16816(acc[j], ah, bh);
                mma16816(acc[j], ah, bl);
                mma16816(acc[j], al, bh);
            }
        }
    }

    // ---------------- epilogue ----------------
    if (m < 2) {
        // Q, K: +bias, split to bf16, store row-major
        __nv_bfloat16* outh = (m == 0) ? g_qh : g_kh;
        __nv_bfloat16* outl = (m == 0) ? g_ql : g_kl;
        #pragma unroll
        for (int j = 0; j < 8; j++) {
            const int col = j * 8 + tg * 2;
            const float b0 = __ldg(bias + col);
            const float b1 = __ldg(bias + col + 1);
            uint32_t h, l;
            size_t r0 = (size_t)(row0 + wrow + g) * DK + col;
            size_t r1 = (size_t)(row0 + wrow + g + 8) * DK + col;
            split2(acc[j][0] + b0, acc[j][1] + b1, h, l);
            *(uint32_t*)&outh[r0] = h; *(uint32_t*)&outl[r0] = l;
            split2(acc[j][2] + b0, acc[j][3] + b1, h, l);
            *(uint32_t*)&outh[r1] = h; *(uint32_t*)&outl[r1] = l;
        }
    } else {
        // V: stage fp32 in smem, then transposed split-bf16 store
        __syncthreads();              // mainloop smem reads done; reuse as stage
        float* stage = (float*)sm;    // [128][66]
        #pragma unroll
        for (int j = 0; j < 8; j++) {
            const int col = j * 8 + tg * 2;
            const float b0 = __ldg(bias + col);
            const float b1 = __ldg(bias + col + 1);
            stage[(wrow + g) * 66 + col]         = acc[j][0] + b0;
            stage[(wrow + g) * 66 + col + 1]     = acc[j][1] + b1;
            stage[(wrow + g + 8) * 66 + col]     = acc[j][2] + b0;
            stage[(wrow + g + 8) * 66 + col + 1] = acc[j][3] + b1;
        }
        __syncthreads();
        const int bb   = row0 >> 11;        // batch
        const int srow = row0 & 2047;       // seq offset within batch
        const int vc = tid >> 2;
        #pragma unroll
        for (int i = 0; i < 16; i++) {
            int sp = (tid & 3) + i * 4;     // 0..63
            int s0 = sp * 2;
            uint32_t h, l;
            split2(stage[s0 * 66 + vc], stage[(s0 + 1) * 66 + vc], h, l);
            size_t off = ((size_t)bb * DK + vc) * SEQ + srow + s0;
            *(uint32_t*)&g_vth[off] = h;
            *(uint32_t*)&g_vtl[off] = l;
        }
    }
}

// ============================ mma.sync flash attention ============================
// grid (32, 4): 64 queries per CTA, 4 warps, each warp owns a 16-query slab.
#define ASTR 72
__global__ __launch_bounds__(128) void attn_mma(float* __restrict__ out)
{
    __shared__ __nv_bfloat16 Kh[64 * ASTR], Kl[64 * ASTR];
    __shared__ __nv_bfloat16 Vh[64 * ASTR], Vl[64 * ASTR];

    const int b  = blockIdx.y;
    const int q0 = blockIdx.x * 64;
    const int tid = threadIdx.x;
    const int wid = tid >> 5;
    const int lane = tid & 31;
    const int g  = lane >> 2;
    const int tg = lane & 3;
    const int wrow = wid * 16;
    const float scale = 0.125f;

    // Q fragments, kept in registers for the whole kernel
    const size_t qbase = (size_t)b * SEQ + q0 + wrow;
    uint32_t qh[4][4], ql[4][4];
    #pragma unroll
    for (int ks = 0; ks < 4; ks++) {
        const int c0 = ks * 16 + tg * 2;
        qh[ks][0] = *(const uint32_t*)&g_qh[(qbase + g    ) * DK + c0];
        qh[ks][1] = *(const uint32_t*)&g_qh[(qbase + g + 8) * DK + c0];
        qh[ks][2] = *(const uint32_t*)&g_qh[(qbase + g    ) * DK + c0 + 8];
        qh[ks][3] = *(const uint32_t*)&g_qh[(qbase + g + 8) * DK + c0 + 8];
        ql[ks][0] = *(const uint32_t*)&g_ql[(qbase + g    ) * DK + c0];
        ql[ks][1] = *(const uint32_t*)&g_ql[(qbase + g + 8) * DK + c0];
        ql[ks][2] = *(const uint32_t*)&g_ql[(qbase + g    ) * DK + c0 + 8];
        ql[ks][3] = *(const uint32_t*)&g_ql[(qbase + g + 8) * DK + c0 + 8];
    }

    float m0 = -1e30f, m1 = -1e30f, l0 = 0.0f, l1 = 0.0f;
    float o[8][4];
    #pragma unroll
    for (int j = 0; j < 8; j++)
        #pragma unroll
        for (int q = 0; q < 4; q++) o[j][q] = 0.0f;

    for (int kb = 0; kb < SEQ / 64; kb++) {
        __syncthreads();
        // stage K (row-major) and Vt (vcol-major) tiles, straight bf16 copy
        #pragma unroll
        for (int it = 0; it < 4; it++) {
            int idx = tid + it * 128;
            int r = idx >> 3, cq = idx & 7;
            size_t koff = ((size_t)b * SEQ + kb * 64 + r) * DK + cq * 8;
            size_t voff = ((size_t)b * DK + r) * SEQ + kb * 64 + cq * 8;
            *(uint4*)&Kh[r * ASTR + cq * 8] = *(const uint4*)&g_kh[koff];
            *(uint4*)&Kl[r * ASTR + cq * 8] = *(const uint4*)&g_kl[koff];
            *(uint4*)&Vh[r * ASTR + cq * 8] = *(const uint4*)&g_vth[voff];
            *(uint4*)&Vl[r * ASTR + cq * 8] = *(const uint4*)&g_vtl[voff];
        }
        __syncthreads();

        // S = Q K^T (split-bf16, 3 terms)
        float sc[8][4];
        #pragma unroll
        for (int j = 0; j < 8; j++)
            #pragma unroll
            for (int q = 0; q < 4; q++) sc[j][q] = 0.0f;
        #pragma unroll
        for (int ks = 0; ks < 4; ks++) {
            const int k0 = ks * 16 + tg * 2;
            #pragma unroll
            for (int j = 0; j < 8; j++) {
                const int krow = j * 8 + g;
                uint32_t bh[2], bl[2];
                bh[0] = *(const uint32_t*)&Kh[krow * ASTR + k0];
                bh[1] = *(const uint32_t*)&Kh[krow * ASTR + k0 + 8];
                bl[0] = *(const uint32_t*)&Kl[krow * ASTR + k0];
                bl[1] = *(const uint32_t*)&Kl[krow * ASTR + k0 + 8];
                mma16816(sc[j], qh[ks], bh);
                mma16816(sc[j], qh[ks], bl);
                mma16816(sc[j], ql[ks], bh);
            }
        }

        // online softmax (rows g and g+8; reduce across 4 tg lanes)
        float mx0 = -1e30f, mx1 = -1e30f;
        #pragma unroll
        for (int j = 0; j < 8; j++) {
            mx0 = fmaxf(mx0, fmaxf(sc[j][0], sc[j][1]));
            mx1 = fmaxf(mx1, fmaxf(sc[j][2], sc[j][3]));
        }
        #pragma unroll
        for (int off = 1; off <= 2; off <<= 1) {
            mx0 = fmaxf(mx0, __shfl_xor_sync(0xffffffffu, mx0, off));
            mx1 = fmaxf(mx1, __shfl_xor_sync(0xffffffffu, mx1, off));
        }
        mx0 *= scale; mx1 *= scale;
        const float mn0 = fmaxf(m0, mx0);
        const float mn1 = fmaxf(m1, mx1);
        const float corr0 = __expf(m0 - mn0);
        const float corr1 = __expf(m1 - mn1);

        float ps0 = 0.0f, ps1 = 0.0f;
        uint32_t ph[8][2], pl[8][2];
        #pragma unroll
        for (int j = 0; j < 8; j++) {
            float p0 = __expf(sc[j][0] * scale - mn0);
            float p1 = __expf(sc[j][1] * scale - mn0);
            float p2 = __expf(sc[j][2] * scale - mn1);
            float p3 = __expf(sc[j][3] * scale - mn1);
            ps0 += p0 + p1; ps1 += p2 + p3;
            split2(p0, p1, ph[j][0], pl[j][0]);
            split2(p2, p3, ph[j][1], pl[j][1]);
        }
        #pragma unroll
        for (int off = 1; off <= 2; off <<= 1) {
            ps0 += __shfl_xor_sync(0xffffffffu, ps0, off);
            ps1 += __shfl_xor_sync(0xffffffffu, ps1, off);
        }
        l0 = l0 * corr0 + ps0;
        l1 = l1 * corr1 + ps1;
        m0 = mn0; m1 = mn1;
        #pragma unroll
        for (int j = 0; j < 8; j++) {
            o[j][0] *= corr0; o[j][1] *= corr0;
            o[j][2] *= corr1; o[j][3] *= corr1;
        }

        // O += P V (P fragments already in registers; split-bf16, 3 terms)
        #pragma unroll
        for (int ks = 0; ks < 4; ks++) {
            const uint32_t pah[4] = {ph[2*ks][0], ph[2*ks][1], ph[2*ks+1][0], ph[2*ks+1][1]};
            const uint32_t pal[4] = {pl[2*ks][0], pl[2*ks][1], pl[2*ks+1][0], pl[2*ks+1][1]};
            const int k0 = ks * 16 + tg * 2;
            #pragma unroll
            for (int j = 0; j < 8; j++) {
                const int vrow = j * 8 + g;
                uint32_t bh[2], bl[2];
                bh[0] = *(const uint32_t*)&Vh[vrow * ASTR + k0];
                bh[1] = *(const uint32_t*)&Vh[vrow * ASTR + k0 + 8];
                bl[0] = *(const uint32_t*)&Vl[vrow * ASTR + k0];
                bl[1] = *(const uint32_t*)&Vl[vrow * ASTR + k0 + 8];
                mma16816(o[j], pah, bh);
                mma16816(o[j], pah, bl);
                mma16816(o[j], pal, bh);
            }
        }
    }

    // normalize + store
    const float inv0 = 1.0f / l0;
    const float inv1 = 1.0f / l1;
    #pragma unroll
    for (int j = 0; j < 8; j++) {
        const int col = j * 8 + tg * 2;
        size_t r0 = ((size_t)b * SEQ + q0 + wrow + g    ) * DK + col;
        size_t r1 = ((size_t)b * SEQ + q0 + wrow + g + 8) * DK + col;
        *(float2*)(out + r0) = make_float2(o[j][0] * inv0, o[j][1] * inv0);
        *(float2*)(out + r1) = make_float2(o[j][2] * inv1, o[j][3] * inv1);
    }
}

// ============================ launch ============================
extern "C" void kernel_launch(void* const* d_in, const int* in_sizes, int n_in,
                              void* d_out, int out_size)
{
    const float* query = (const float*)d_in[0];
    const float* key   = (const float*)d_in[1];
    const float* value = (const float*)d_in[2];
    const float* Wq    = (const float*)d_in[3];
    const float* bq    = (const float*)d_in[4];
    const float* Wk    = (const float*)d_in[5];
    const float* bk    = (const float*)d_in[6];
    const float* Wv    = (const float*)d_in[7];
    const float* bv    = (const float*)d_in[8];
    float* out = (float*)d_out;

    const int proj_smem = PS_ELEMS * (int)sizeof(__nv_bfloat16);  // 57344
    static bool attr_set = false;
    if (!attr_set) {
        cudaFuncSetAttribute(proj_mma,
                             cudaFuncAttributeMaxDynamicSharedMemorySize, proj_smem);
        attr_set = true;
    }

    prep_w<<<dim3(3, 64), 256>>>(Wq, Wk, Wv);
    proj_mma<<<dim3(64, 3), 256, proj_smem>>>(query, key, value, bq, bk, bv);
    attn_mma<<<dim3(SEQ / 64, BATCH), 128>>>(out);
}

// round 6
// speedup vs baseline: 3.0922x; 1.3006x over previous
#include <cuda_runtime.h>
#include <cuda_bf16.h>
#include <cstdint>
#include <math.h>

#define BATCH  4
#define SEQ    2048
#define DMODEL 1024
#define DK     64

// projected activations, split bf16
__device__ __align__(16) __nv_bfloat16 g_qh[BATCH * SEQ * DK];
__device__ __align__(16) __nv_bfloat16 g_ql[BATCH * SEQ * DK];
__device__ __align__(16) __nv_bfloat16 g_kh[BATCH * SEQ * DK];
__device__ __align__(16) __nv_bfloat16 g_kl[BATCH * SEQ * DK];
// V transposed: [batch][vcol][seq]
__device__ __align__(16) __nv_bfloat16 g_vth[BATCH * DK * SEQ];
__device__ __align__(16) __nv_bfloat16 g_vtl[BATCH * DK * SEQ];
// pre-transposed + bf16-split weights: [matrix][n][k]
__device__ __align__(16) __nv_bfloat16 g_wt_hi[3 * DK * DMODEL];
__device__ __align__(16) __nv_bfloat16 g_wt_lo[3 * DK * DMODEL];

// ============================ mma.sync helper ============================
__device__ __forceinline__ void mma16816(float c[4], const uint32_t a[4],
                                         const uint32_t b[2]) {
    asm volatile(
        "mma.sync.aligned.m16n8k16.row.col.f32.bf16.bf16.f32 "
        "{%0, %1, %2, %3}, {%4, %5, %6, %7}, {%8, %9}, {%0, %1, %2, %3};"
        : "+f"(c[0]), "+f"(c[1]), "+f"(c[2]), "+f"(c[3])
        : "r"(a[0]), "r"(a[1]), "r"(a[2]), "r"(a[3]), "r"(b[0]), "r"(b[1]));
}

// Fast Dekker split: hi = truncate-to-bf16 (exact residual), lo = rn(residual).
// 6 instrs per 2 elements: PRMT + 2 LOP + 2 FADD + CVT.BF16X2.
__device__ __forceinline__ void fsplit2(float a, float b, uint32_t& hi, uint32_t& lo) {
    uint32_t ua = __float_as_uint(a), ub = __float_as_uint(b);
    hi = __byte_perm(ua, ub, 0x7632);
    float ra = a - __uint_as_float(ua & 0xffff0000u);
    float rb = b - __uint_as_float(ub & 0xffff0000u);
    __nv_bfloat162 l2 = __floats2bfloat162_rn(ra, rb);
    lo = *reinterpret_cast<uint32_t*>(&l2);
}

// ============================ prep: transpose + split weights ============================
__global__ __launch_bounds__(256) void prep_w(const float* __restrict__ Wq,
                                              const float* __restrict__ Wk,
                                              const float* __restrict__ Wv)
{
    const int m = blockIdx.x;
    const float* W = (m == 0) ? Wq : (m == 1) ? Wk : Wv;   // [1024, 64] row-major
    __nv_bfloat16* th = g_wt_hi + m * DK * DMODEL;
    __nv_bfloat16* tl = g_wt_lo + m * DK * DMODEL;
    int gi4 = (blockIdx.y * 256 + threadIdx.x) * 4;
    float4 w4 = *(const float4*)(W + gi4);
    const float wv[4] = {w4.x, w4.y, w4.z, w4.w};
    #pragma unroll
    for (int e = 0; e < 4; e++) {
        int gi = gi4 + e;
        int k = gi >> 6, n = gi & 63;
        uint32_t u = __float_as_uint(wv[e]);
        __nv_bfloat16 h = __ushort_as_bfloat16((unsigned short)(u >> 16));  // truncate
        float r = wv[e] - __uint_as_float(u & 0xffff0000u);                 // exact
        th[n * DMODEL + k] = h;
        tl[n * DMODEL + k] = __float2bfloat16_rn(r);
    }
}

// ============================ mma.sync projection ============================
#define XSTR 72
#define WSTR 80
static const int PS_XH = 0;
static const int PS_XL = 128 * XSTR;
static const int PS_WH = 2 * 128 * XSTR;
static const int PS_WL = 2 * 128 * XSTR + 64 * WSTR;
static const int PS_ELEMS = 2 * 128 * XSTR + 2 * 64 * WSTR;   // 28672 elems = 57344 B

__device__ __forceinline__ void proj_ldg(const float* __restrict__ X, int row0, int c,
                                         int tid,
                                         const __nv_bfloat16* __restrict__ wh,
                                         const __nv_bfloat16* __restrict__ wl,
                                         float4 xr[8], uint4 wrh[2], uint4 wrl[2])
{
    #pragma unroll
    for (int it = 0; it < 8; it++) {
        int idx = tid + it * 256;
        int r = idx >> 4, c4 = idx & 15;
        xr[it] = *(const float4*)(X + (size_t)(row0 + r) * DMODEL + c * 64 + c4 * 4);
    }
    #pragma unroll
    for (int it = 0; it < 2; it++) {
        int idx = tid + it * 256;
        int n = idx >> 3, c8 = idx & 7;
        wrh[it] = *(const uint4*)(wh + n * DMODEL + c * 64 + c8 * 8);
        wrl[it] = *(const uint4*)(wl + n * DMODEL + c * 64 + c8 * 8);
    }
}

__global__ __launch_bounds__(256) void proj_mma(
    const float* __restrict__ Xq, const float* __restrict__ Xk,
    const float* __restrict__ Xv,
    const float* __restrict__ bq, const float* __restrict__ bk,
    const float* __restrict__ bv)
{
    extern __shared__ __nv_bfloat16 sm[];
    __nv_bfloat16* Xh = sm + PS_XH;
    __nv_bfloat16* Xl = sm + PS_XL;
    __nv_bfloat16* Wh = sm + PS_WH;
    __nv_bfloat16* Wl = sm + PS_WL;

    const int tid = threadIdx.x;
    const int wid = tid >> 5;
    const int lane = tid & 31;
    const int g  = lane >> 2;
    const int tg = lane & 3;
    const int m = blockIdx.y;
    const int row0 = blockIdx.x * 128;

    const float* X    = (m == 0) ? Xq : (m == 1) ? Xk : Xv;
    const float* bias = (m == 0) ? bq : (m == 1) ? bk : bv;
    const __nv_bfloat16* wh = g_wt_hi + m * DK * DMODEL;
    const __nv_bfloat16* wl = g_wt_lo + m * DK * DMODEL;

    float acc[8][4];
    #pragma unroll
    for (int j = 0; j < 8; j++)
        #pragma unroll
        for (int q = 0; q < 4; q++) acc[j][q] = 0.0f;

    float4 xr[8]; uint4 wrh[2], wrl[2];
    proj_ldg(X, row0, 0, tid, wh, wl, xr, wrh, wrl);

    const int wrow = wid * 16;

    for (int c = 0; c < 16; c++) {
        if (c > 0) __syncthreads();

        #pragma unroll
        for (int it = 0; it < 8; it++) {
            int idx = tid + it * 256;
            int r = idx >> 4, c4 = idx & 15;
            uint32_t h0, l0, h1, l1;
            fsplit2(xr[it].x, xr[it].y, h0, l0);
            fsplit2(xr[it].z, xr[it].w, h1, l1);
            *(uint2*)&Xh[r * XSTR + c4 * 4] = make_uint2(h0, h1);
            *(uint2*)&Xl[r * XSTR + c4 * 4] = make_uint2(l0, l1);
        }
        #pragma unroll
        for (int it = 0; it < 2; it++) {
            int idx = tid + it * 256;
            int n = idx >> 3, c8 = idx & 7;
            *(uint4*)&Wh[n * WSTR + c8 * 8] = wrh[it];
            *(uint4*)&Wl[n * WSTR + c8 * 8] = wrl[it];
        }
        __syncthreads();

        if (c < 15)
            proj_ldg(X, row0, c + 1, tid, wh, wl, xr, wrh, wrl);

        #pragma unroll
        for (int ks = 0; ks < 4; ks++) {
            const int k0 = ks * 16;
            uint32_t ah[4], al[4];
            ah[0] = *(const uint32_t*)&Xh[(wrow + g    ) * XSTR + k0 + tg * 2];
            ah[1] = *(const uint32_t*)&Xh[(wrow + g + 8) * XSTR + k0 + tg * 2];
            ah[2] = *(const uint32_t*)&Xh[(wrow + g    ) * XSTR + k0 + 8 + tg * 2];
            ah[3] = *(const uint32_t*)&Xh[(wrow + g + 8) * XSTR + k0 + 8 + tg * 2];
            al[0] = *(const uint32_t*)&Xl[(wrow + g    ) * XSTR + k0 + tg * 2];
            al[1] = *(const uint32_t*)&Xl[(wrow + g + 8) * XSTR + k0 + tg * 2];
            al[2] = *(const uint32_t*)&Xl[(wrow + g    ) * XSTR + k0 + 8 + tg * 2];
            al[3] = *(const uint32_t*)&Xl[(wrow + g + 8) * XSTR + k0 + 8 + tg * 2];
            #pragma unroll
            for (int j = 0; j < 8; j++) {
                const int n = j * 8 + g;
                uint32_t bh[2], bl[2];
                bh[0] = *(const uint32_t*)&Wh[n * WSTR + k0 + tg * 2];
                bh[1] = *(const uint32_t*)&Wh[n * WSTR + k0 + 8 + tg * 2];
                bl[0] = *(const uint32_t*)&Wl[n * WSTR + k0 + tg * 2];
                bl[1] = *(const uint32_t*)&Wl[n * WSTR + k0 + 8 + tg * 2];
                mma16816(acc[j], ah, bh);
                mma16816(acc[j], ah, bl);
                mma16816(acc[j], al, bh);
            }
        }
    }

    // ---------------- epilogue ----------------
    if (m < 2) {
        __nv_bfloat16* outh = (m == 0) ? g_qh : g_kh;
        __nv_bfloat16* outl = (m == 0) ? g_ql : g_kl;
        #pragma unroll
        for (int j = 0; j < 8; j++) {
            const int col = j * 8 + tg * 2;
            const float b0 = __ldg(bias + col);
            const float b1 = __ldg(bias + col + 1);
            uint32_t h, l;
            size_t r0 = (size_t)(row0 + wrow + g) * DK + col;
            size_t r1 = (size_t)(row0 + wrow + g + 8) * DK + col;
            fsplit2(acc[j][0] + b0, acc[j][1] + b1, h, l);
            *(uint32_t*)&outh[r0] = h; *(uint32_t*)&outl[r0] = l;
            fsplit2(acc[j][2] + b0, acc[j][3] + b1, h, l);
            *(uint32_t*)&outh[r1] = h; *(uint32_t*)&outl[r1] = l;
        }
    } else {
        // V: stage fp32 in smem, then transposed split-bf16 store
        __syncthreads();
        float* stage = (float*)sm;    // [128][66]
        #pragma unroll
        for (int j = 0; j < 8; j++) {
            const int col = j * 8 + tg * 2;
            const float b0 = __ldg(bias + col);
            const float b1 = __ldg(bias + col + 1);
            stage[(wrow + g) * 66 + col]         = acc[j][0] + b0;
            stage[(wrow + g) * 66 + col + 1]     = acc[j][1] + b1;
            stage[(wrow + g + 8) * 66 + col]     = acc[j][2] + b0;
            stage[(wrow + g + 8) * 66 + col + 1] = acc[j][3] + b1;
        }
        __syncthreads();
        const int bb   = row0 >> 11;
        const int srow = row0 & 2047;
        const int vc = tid >> 2;
        #pragma unroll
        for (int i = 0; i < 16; i++) {
            int sp = (tid & 3) + i * 4;
            int s0 = sp * 2;
            uint32_t h, l;
            fsplit2(stage[s0 * 66 + vc], stage[(s0 + 1) * 66 + vc], h, l);
            size_t off = ((size_t)bb * DK + vc) * SEQ + srow + s0;
            *(uint32_t*)&g_vth[off] = h;
            *(uint32_t*)&g_vtl[off] = l;
        }
    }
}

// ============================ mma.sync flash attention ============================
// grid (32, 4): 64 queries per CTA, 8 warps. Warps 0-3 take even 64-key tiles,
// warps 4-7 take odd tiles (double-buffered smem); split-softmax merge at end.
#define ASTR 72
static const int AT_ELEMS = 8 * 64 * ASTR;          // 36864 bf16 = 73728 B

__global__ __launch_bounds__(256) void attn_mma(float* __restrict__ out)
{
    extern __shared__ __nv_bfloat16 asmem[];
    __nv_bfloat16* Kh = asmem;                      // [2][64*ASTR]
    __nv_bfloat16* Kl = Kh + 2 * 64 * ASTR;
    __nv_bfloat16* Vh = Kl + 2 * 64 * ASTR;
    __nv_bfloat16* Vl = Vh + 2 * 64 * ASTR;

    const int b  = blockIdx.y;
    const int q0 = blockIdx.x * 64;
    const int tid = threadIdx.x;
    const int wid = tid >> 5;
    const int lane = tid & 31;
    const int g  = lane >> 2;
    const int tg = lane & 3;
    const int qw = wid & 3;          // query slab
    const int half = wid >> 2;       // key-half
    const int wrow = qw * 16;
    const int hb = half * 64 * ASTR; // this half's buffer offset
    const float scale = 0.125f;

    // Q fragments (both halves load the same queries)
    const size_t qbase = (size_t)b * SEQ + q0 + wrow;
    uint32_t qh[4][4], ql[4][4];
    #pragma unroll
    for (int ks = 0; ks < 4; ks++) {
        const int c0 = ks * 16 + tg * 2;
        qh[ks][0] = *(const uint32_t*)&g_qh[(qbase + g    ) * DK + c0];
        qh[ks][1] = *(const uint32_t*)&g_qh[(qbase + g + 8) * DK + c0];
        qh[ks][2] = *(const uint32_t*)&g_qh[(qbase + g    ) * DK + c0 + 8];
        qh[ks][3] = *(const uint32_t*)&g_qh[(qbase + g + 8) * DK + c0 + 8];
        ql[ks][0] = *(const uint32_t*)&g_ql[(qbase + g    ) * DK + c0];
        ql[ks][1] = *(const uint32_t*)&g_ql[(qbase + g + 8) * DK + c0];
        ql[ks][2] = *(const uint32_t*)&g_ql[(qbase + g    ) * DK + c0 + 8];
        ql[ks][3] = *(const uint32_t*)&g_ql[(qbase + g + 8) * DK + c0 + 8];
    }

    float m0 = -1e30f, m1 = -1e30f, l0 = 0.0f, l1 = 0.0f;
    float o[8][4];
    #pragma unroll
    for (int j = 0; j < 8; j++)
        #pragma unroll
        for (int q = 0; q < 4; q++) o[j][q] = 0.0f;

    for (int it = 0; it < 16; it++) {
        __syncthreads();
        // stage two 64-key tiles (buffer bf = tile 2*it+bf)
        #pragma unroll
        for (int t = 0; t < 2; t++) {
            int idx = tid + t * 256;          // 0..511
            int r = idx >> 3, cq = idx & 7;
            #pragma unroll
            for (int bf = 0; bf < 2; bf++) {
                int kb = it * 2 + bf;
                size_t koff = ((size_t)b * SEQ + kb * 64 + r) * DK + cq * 8;
                size_t voff = ((size_t)b * DK + r) * SEQ + kb * 64 + cq * 8;
                int so = bf * 64 * ASTR + r * ASTR + cq * 8;
                *(uint4*)&Kh[so] = *(const uint4*)&g_kh[koff];
                *(uint4*)&Kl[so] = *(const uint4*)&g_kl[koff];
                *(uint4*)&Vh[so] = *(const uint4*)&g_vth[voff];
                *(uint4*)&Vl[so] = *(const uint4*)&g_vtl[voff];
            }
        }
        __syncthreads();

        // S = Q K^T (split-bf16, 3 terms)
        float sc[8][4];
        #pragma unroll
        for (int j = 0; j < 8; j++)
            #pragma unroll
            for (int q = 0; q < 4; q++) sc[j][q] = 0.0f;
        #pragma unroll
        for (int ks = 0; ks < 4; ks++) {
            const int k0 = ks * 16 + tg * 2;
            #pragma unroll
            for (int j = 0; j < 8; j++) {
                const int krow = hb + (j * 8 + g) * ASTR;
                uint32_t bh[2], bl[2];
                bh[0] = *(const uint32_t*)&Kh[krow + k0];
                bh[1] = *(const uint32_t*)&Kh[krow + k0 + 8];
                bl[0] = *(const uint32_t*)&Kl[krow + k0];
                bl[1] = *(const uint32_t*)&Kl[krow + k0 + 8];
                mma16816(sc[j], qh[ks], bh);
                mma16816(sc[j], qh[ks], bl);
                mma16816(sc[j], ql[ks], bh);
            }
        }

        // online softmax (rows g and g+8; reduce across 4 tg lanes)
        float mx0 = -1e30f, mx1 = -1e30f;
        #pragma unroll
        for (int j = 0; j < 8; j++) {
            mx0 = fmaxf(mx0, fmaxf(sc[j][0], sc[j][1]));
            mx1 = fmaxf(mx1, fmaxf(sc[j][2], sc[j][3]));
        }
        #pragma unroll
        for (int off = 1; off <= 2; off <<= 1) {
            mx0 = fmaxf(mx0, __shfl_xor_sync(0xffffffffu, mx0, off));
            mx1 = fmaxf(mx1, __shfl_xor_sync(0xffffffffu, mx1, off));
        }
        mx0 *= scale; mx1 *= scale;
        const float mn0 = fmaxf(m0, mx0);
        const float mn1 = fmaxf(m1, mx1);
        const float corr0 = __expf(m0 - mn0);
        const float corr1 = __expf(m1 - mn1);

        float ps0 = 0.0f, ps1 = 0.0f;
        uint32_t ph[8][2], pl[8][2];
        #pragma unroll
        for (int j = 0; j < 8; j++) {
            float p0 = __expf(sc[j][0] * scale - mn0);
            float p1 = __expf(sc[j][1] * scale - mn0);
            float p2 = __expf(sc[j][2] * scale - mn1);
            float p3 = __expf(sc[j][3] * scale - mn1);
            ps0 += p0 + p1; ps1 += p2 + p3;
            fsplit2(p0, p1, ph[j][0], pl[j][0]);
            fsplit2(p2, p3, ph[j][1], pl[j][1]);
        }
        #pragma unroll
        for (int off = 1; off <= 2; off <<= 1) {
            ps0 += __shfl_xor_sync(0xffffffffu, ps0, off);
            ps1 += __shfl_xor_sync(0xffffffffu, ps1, off);
        }
        l0 = l0 * corr0 + ps0;
        l1 = l1 * corr1 + ps1;
        m0 = mn0; m1 = mn1;
        #pragma unroll
        for (int j = 0; j < 8; j++) {
            o[j][0] *= corr0; o[j][1] *= corr0;
            o[j][2] *= corr1; o[j][3] *= corr1;
        }

        // O += P V (split-bf16, 3 terms)
        #pragma unroll
        for (int ks = 0; ks < 4; ks++) {
            const uint32_t pah[4] = {ph[2*ks][0], ph[2*ks][1], ph[2*ks+1][0], ph[2*ks+1][1]};
            const uint32_t pal[4] = {pl[2*ks][0], pl[2*ks][1], pl[2*ks+1][0], pl[2*ks+1][1]};
            const int k0 = ks * 16 + tg * 2;
            #pragma unroll
            for (int j = 0; j < 8; j++) {
                const int vrow = hb + (j * 8 + g) * ASTR;
                uint32_t bh[2], bl[2];
                bh[0] = *(const uint32_t*)&Vh[vrow + k0];
                bh[1] = *(const uint32_t*)&Vh[vrow + k0 + 8];
                bl[0] = *(const uint32_t*)&Vl[vrow + k0];
                bl[1] = *(const uint32_t*)&Vl[vrow + k0 + 8];
                mma16816(o[j], pah, bh);
                mma16816(o[j], pah, bl);
                mma16816(o[j], pal, bh);
            }
        }
    }

    // ---------------- split-softmax merge (halves 1 -> 0) ----------------
    __syncthreads();
    float* buf = (float*)asmem;     // reuse: [4][32][36]
    if (half) {
        float* p = buf + ((size_t)qw * 32 + lane) * 36;
        #pragma unroll
        for (int j = 0; j < 8; j++) {
            p[j * 4 + 0] = o[j][0]; p[j * 4 + 1] = o[j][1];
            p[j * 4 + 2] = o[j][2]; p[j * 4 + 3] = o[j][3];
        }
        p[32] = m0; p[33] = m1; p[34] = l0; p[35] = l1;
    }
    __syncthreads();
    if (!half) {
        const float* p = buf + ((size_t)qw * 32 + lane) * 36;
        const float mB0 = p[32], mB1 = p[33], lB0 = p[34], lB1 = p[35];
        const float mn0 = fmaxf(m0, mB0), mn1 = fmaxf(m1, mB1);
        const float cA0 = __expf(m0 - mn0), cB0 = __expf(mB0 - mn0);
        const float cA1 = __expf(m1 - mn1), cB1 = __expf(mB1 - mn1);
        const float inv0 = 1.0f / (l0 * cA0 + lB0 * cB0);
        const float inv1 = 1.0f / (l1 * cA1 + lB1 * cB1);
        #pragma unroll
        for (int j = 0; j < 8; j++) {
            const int col = j * 8 + tg * 2;
            size_t r0 = ((size_t)b * SEQ + q0 + wrow + g    ) * DK + col;
            size_t r1 = ((size_t)b * SEQ + q0 + wrow + g + 8) * DK + col;
            float o0 = (o[j][0] * cA0 + p[j * 4 + 0] * cB0) * inv0;
            float o1 = (o[j][1] * cA0 + p[j * 4 + 1] * cB0) * inv0;
            float o2 = (o[j][2] * cA1 + p[j * 4 + 2] * cB1) * inv1;
            float o3 = (o[j][3] * cA1 + p[j * 4 + 3] * cB1) * inv1;
            *(float2*)(out + r0) = make_float2(o0, o1);
            *(float2*)(out + r1) = make_float2(o2, o3);
        }
    }
}

// ============================ launch ============================
extern "C" void kernel_launch(void* const* d_in, const int* in_sizes, int n_in,
                              void* d_out, int out_size)
{
    const float* query = (const float*)d_in[0];
    const float* key   = (const float*)d_in[1];
    const float* value = (const float*)d_in[2];
    const float* Wq    = (const float*)d_in[3];
    const float* bq    = (const float*)d_in[4];
    const float* Wk    = (const float*)d_in[5];
    const float* bk    = (const float*)d_in[6];
    const float* Wv    = (const float*)d_in[7];
    const float* bv    = (const float*)d_in[8];
    float* out = (float*)d_out;

    const int proj_smem = PS_ELEMS * (int)sizeof(__nv_bfloat16);  // 57344
    const int attn_smem = AT_ELEMS * (int)sizeof(__nv_bfloat16);  // 73728
    static bool attr_set = false;
    if (!attr_set) {
        cudaFuncSetAttribute(proj_mma,
                             cudaFuncAttributeMaxDynamicSharedMemorySize, proj_smem);
        cudaFuncSetAttribute(attn_mma,
                             cudaFuncAttributeMaxDynamicSharedMemorySize, attn_smem);
        attr_set = true;
    }

    prep_w<<<dim3(3, 64), 256>>>(Wq, Wk, Wv);
    proj_mma<<<dim3(64, 3), 256, proj_smem>>>(query, key, value, bq, bk, bv);
    attn_mma<<<dim3(SEQ / 64, BATCH), 256, attn_smem>>>(out);
}

// round 7
// speedup vs baseline: 3.9209x; 1.2680x over previous
#include <cuda_runtime.h>
#include <cuda_bf16.h>
#include <cstdint>
#include <math.h>

#define BATCH  4
#define SEQ    2048
#define DMODEL 1024
#define DK     64

// projected activations, split bf16
__device__ __align__(16) __nv_bfloat16 g_qh[BATCH * SEQ * DK];
__device__ __align__(16) __nv_bfloat16 g_ql[BATCH * SEQ * DK];
__device__ __align__(16) __nv_bfloat16 g_kh[BATCH * SEQ * DK];
__device__ __align__(16) __nv_bfloat16 g_kl[BATCH * SEQ * DK];
// V transposed: [batch][vcol][seq]
__device__ __align__(16) __nv_bfloat16 g_vth[BATCH * DK * SEQ];
__device__ __align__(16) __nv_bfloat16 g_vtl[BATCH * DK * SEQ];
// pre-transposed + bf16-split weights: [matrix][n][k]
__device__ __align__(16) __nv_bfloat16 g_wt_hi[3 * DK * DMODEL];
__device__ __align__(16) __nv_bfloat16 g_wt_lo[3 * DK * DMODEL];

// ============================ PTX helpers ============================
__device__ __forceinline__ uint32_t smem_u32(const void* p) {
    uint32_t a;
    asm("{ .reg .u64 t; cvta.to.shared.u64 t, %1; cvt.u32.u64 %0, t; }"
        : "=r"(a) : "l"(p));
    return a;
}
__device__ __forceinline__ void mma16816s(float c[4], uint32_t a0, uint32_t a1,
                                          uint32_t a2, uint32_t a3,
                                          uint32_t b0, uint32_t b1) {
    asm volatile(
        "mma.sync.aligned.m16n8k16.row.col.f32.bf16.bf16.f32 "
        "{%0, %1, %2, %3}, {%4, %5, %6, %7}, {%8, %9}, {%0, %1, %2, %3};"
        : "+f"(c[0]), "+f"(c[1]), "+f"(c[2]), "+f"(c[3])
        : "r"(a0), "r"(a1), "r"(a2), "r"(a3), "r"(b0), "r"(b1));
}
#define LDSM_X4(r0, r1, r2, r3, addr) \
    asm volatile("ldmatrix.sync.aligned.m8n8.x4.shared.b16 {%0,%1,%2,%3}, [%4];" \
        : "=r"(r0), "=r"(r1), "=r"(r2), "=r"(r3) : "r"(addr))
#define CP_ASYNC16(dst, src) \
    asm volatile("cp.async.cg.shared.global [%0], [%1], 16;" \
        :: "r"(dst), "l"(src) : "memory")
#define CP_COMMIT() asm volatile("cp.async.commit_group;" ::: "memory")
#define CP_WAIT0()  asm volatile("cp.async.wait_group 0;" ::: "memory")

// Fast Dekker split: hi = truncate-to-bf16 (exact residual), lo = rn(residual).
__device__ __forceinline__ void fsplit2(float a, float b, uint32_t& hi, uint32_t& lo) {
    uint32_t ua = __float_as_uint(a), ub = __float_as_uint(b);
    hi = __byte_perm(ua, ub, 0x7632);
    float ra = a - __uint_as_float(ua & 0xffff0000u);
    float rb = b - __uint_as_float(ub & 0xffff0000u);
    __nv_bfloat162 l2 = __floats2bfloat162_rn(ra, rb);
    lo = *reinterpret_cast<uint32_t*>(&l2);
}

// ============================ prep: transpose + split weights ============================
// grid (3, 16): CTA handles 64 k-rows; smem-staged transpose -> coalesced stores.
__global__ __launch_bounds__(256) void prep_w(const float* __restrict__ Wq,
                                              const float* __restrict__ Wk,
                                              const float* __restrict__ Wv)
{
    __shared__ float stage[64][65];
    const int m = blockIdx.x;
    const float* W = (m == 0) ? Wq : (m == 1) ? Wk : Wv;   // [1024, 64] row-major
    __nv_bfloat16* th = g_wt_hi + m * DK * DMODEL;
    __nv_bfloat16* tl = g_wt_lo + m * DK * DMODEL;
    const int tid = threadIdx.x;
    const int k0 = blockIdx.y * 64;

    #pragma unroll
    for (int i = 0; i < 4; i++) {
        int idx = i * 256 + tid;
        int k = idx >> 4, n4 = (idx & 15) * 4;
        float4 w4 = *(const float4*)(W + (size_t)(k0 + k) * 64 + n4);
        stage[k][n4]     = w4.x;
        stage[k][n4 + 1] = w4.y;
        stage[k][n4 + 2] = w4.z;
        stage[k][n4 + 3] = w4.w;
    }
    __syncthreads();

    const int n = tid >> 2, kq = tid & 3;
    uint32_t h[8], l[8];
    #pragma unroll
    for (int e = 0; e < 8; e++) {
        float a = stage[kq * 16 + 2 * e][n];
        float b = stage[kq * 16 + 2 * e + 1][n];
        uint32_t ua = __float_as_uint(a), ub = __float_as_uint(b);
        h[e] = __byte_perm(ua, ub, 0x7632);
        float ra = a - __uint_as_float(ua & 0xffff0000u);
        float rb = b - __uint_as_float(ub & 0xffff0000u);
        __nv_bfloat162 l2 = __floats2bfloat162_rn(ra, rb);
        l[e] = *reinterpret_cast<uint32_t*>(&l2);
    }
    size_t off = (size_t)n * DMODEL + k0 + kq * 16;
    *(uint4*)&th[off]     = make_uint4(h[0], h[1], h[2], h[3]);
    *(uint4*)&th[off + 8] = make_uint4(h[4], h[5], h[6], h[7]);
    *(uint4*)&tl[off]     = make_uint4(l[0], l[1], l[2], l[3]);
    *(uint4*)&tl[off + 8] = make_uint4(l[4], l[5], l[6], l[7]);
}

// ============================ mma.sync projection ============================
#define XSTR 72
#define WSTR 72
static const int PS_XH = 0;
static const int PS_XL = 128 * XSTR;                         // 9216
static const int PS_WH = 2 * 128 * XSTR;                     // 18432
static const int PS_WL = 2 * 128 * XSTR + 64 * WSTR;         // 23040
static const int PS_ELEMS = 2 * 128 * XSTR + 2 * 64 * WSTR;  // 27648 elems = 55296 B

__device__ __forceinline__ void proj_ldg(const float* __restrict__ X, int row0, int c,
                                         int tid,
                                         const __nv_bfloat16* __restrict__ wh,
                                         const __nv_bfloat16* __restrict__ wl,
                                         float4 xr[8], uint4 wrh[2], uint4 wrl[2])
{
    #pragma unroll
    for (int it = 0; it < 8; it++) {
        int idx = tid + it * 256;
        int r = idx >> 4, c4 = idx & 15;
        xr[it] = *(const float4*)(X + (size_t)(row0 + r) * DMODEL + c * 64 + c4 * 4);
    }
    #pragma unroll
    for (int it = 0; it < 2; it++) {
        int idx = tid + it * 256;
        int n = idx >> 3, c8 = idx & 7;
        wrh[it] = *(const uint4*)(wh + n * DMODEL + c * 64 + c8 * 8);
        wrl[it] = *(const uint4*)(wl + n * DMODEL + c * 64 + c8 * 8);
    }
}

__global__ __launch_bounds__(256) void proj_mma(
    const float* __restrict__ Xq, const float* __restrict__ Xk,
    const float* __restrict__ Xv,
    const float* __restrict__ bq, const float* __restrict__ bk,
    const float* __restrict__ bv)
{
    extern __shared__ __nv_bfloat16 sm[];
    __nv_bfloat16* Xh = sm + PS_XH;
    __nv_bfloat16* Xl = sm + PS_XL;
    __nv_bfloat16* Wh = sm + PS_WH;
    __nv_bfloat16* Wl = sm + PS_WL;

    const int tid = threadIdx.x;
    const int wid = tid >> 5;
    const int lane = tid & 31;
    const int g  = lane >> 2;
    const int tg = lane & 3;
    const int m = blockIdx.y;
    const int row0 = blockIdx.x * 128;

    const float* X    = (m == 0) ? Xq : (m == 1) ? Xk : Xv;
    const float* bias = (m == 0) ? bq : (m == 1) ? bk : bv;
    const __nv_bfloat16* wh = g_wt_hi + m * DK * DMODEL;
    const __nv_bfloat16* wl = g_wt_lo + m * DK * DMODEL;

    float acc[8][4];
    #pragma unroll
    for (int j = 0; j < 8; j++)
        #pragma unroll
        for (int q = 0; q < 4; q++) acc[j][q] = 0.0f;

    float4 xr[8]; uint4 wrh[2], wrl[2];
    proj_ldg(X, row0, 0, tid, wh, wl, xr, wrh, wrl);

    const int wrow = wid * 16;

    // ldmatrix lane addressing
    const uint32_t sb = smem_u32(sm);
    const int arow = (lane & 7) + ((lane >> 3) & 1) * 8;
    const int acol = ((lane >> 4) & 1) * 8;
    const uint32_t xh_a = sb + (uint32_t)(((wrow + arow) * XSTR + acol) * 2) + PS_XH * 2;
    const uint32_t xl_a = sb + (uint32_t)(((wrow + arow) * XSTR + acol) * 2) + PS_XL * 2;
    const int brow = (lane & 7) + ((lane >> 4) & 1) * 8;
    const int bcol = ((lane >> 3) & 1) * 8;
    const uint32_t wh_a = sb + (uint32_t)((brow * WSTR + bcol) * 2) + PS_WH * 2;
    const uint32_t wl_a = sb + (uint32_t)((brow * WSTR + bcol) * 2) + PS_WL * 2;

    for (int c = 0; c < 16; c++) {
        if (c > 0) __syncthreads();

        #pragma unroll
        for (int it = 0; it < 8; it++) {
            int idx = tid + it * 256;
            int r = idx >> 4, c4 = idx & 15;
            uint32_t h0, l0, h1, l1;
            fsplit2(xr[it].x, xr[it].y, h0, l0);
            fsplit2(xr[it].z, xr[it].w, h1, l1);
            *(uint2*)&Xh[r * XSTR + c4 * 4] = make_uint2(h0, h1);
            *(uint2*)&Xl[r * XSTR + c4 * 4] = make_uint2(l0, l1);
        }
        #pragma unroll
        for (int it = 0; it < 2; it++) {
            int idx = tid + it * 256;
            int n = idx >> 3, c8 = idx & 7;
            *(uint4*)&Wh[n * WSTR + c8 * 8] = wrh[it];
            *(uint4*)&Wl[n * WSTR + c8 * 8] = wrl[it];
        }
        __syncthreads();

        if (c < 15)
            proj_ldg(X, row0, c + 1, tid, wh, wl, xr, wrh, wrl);

        #pragma unroll
        for (int ks = 0; ks < 4; ks++) {
            uint32_t ah0, ah1, ah2, ah3, al0, al1, al2, al3;
            LDSM_X4(ah0, ah1, ah2, ah3, xh_a + ks * 32);
            LDSM_X4(al0, al1, al2, al3, xl_a + ks * 32);
            #pragma unroll
            for (int t = 0; t < 4; t++) {
                const uint32_t toff = t * (16 * WSTR * 2) + ks * 32;
                uint32_t bh0, bh1, bh2, bh3, bl0, bl1, bl2, bl3;
                LDSM_X4(bh0, bh1, bh2, bh3, wh_a + toff);
                LDSM_X4(bl0, bl1, bl2, bl3, wl_a + toff);
                mma16816s(acc[2*t],   ah0, ah1, ah2, ah3, bh0, bh1);
                mma16816s(acc[2*t],   ah0, ah1, ah2, ah3, bl0, bl1);
                mma16816s(acc[2*t],   al0, al1, al2, al3, bh0, bh1);
                mma16816s(acc[2*t+1], ah0, ah1, ah2, ah3, bh2, bh3);
                mma16816s(acc[2*t+1], ah0, ah1, ah2, ah3, bl2, bl3);
                mma16816s(acc[2*t+1], al0, al1, al2, al3, bh2, bh3);
            }
        }
    }

    // ---------------- epilogue ----------------
    if (m < 2) {
        __nv_bfloat16* outh = (m == 0) ? g_qh : g_kh;
        __nv_bfloat16* outl = (m == 0) ? g_ql : g_kl;
        #pragma unroll
        for (int j = 0; j < 8; j++) {
            const int col = j * 8 + tg * 2;
            const float b0 = __ldg(bias + col);
            const float b1 = __ldg(bias + col + 1);
            uint32_t h, l;
            size_t r0 = (size_t)(row0 + wrow + g) * DK + col;
            size_t r1 = (size_t)(row0 + wrow + g + 8) * DK + col;
            fsplit2(acc[j][0] + b0, acc[j][1] + b1, h, l);
            *(uint32_t*)&outh[r0] = h; *(uint32_t*)&outl[r0] = l;
            fsplit2(acc[j][2] + b0, acc[j][3] + b1, h, l);
            *(uint32_t*)&outh[r1] = h; *(uint32_t*)&outl[r1] = l;
        }
    } else {
        // V: stage fp32 in smem, then transposed split-bf16 store
        __syncthreads();
        float* stage = (float*)sm;    // [128][66]
        #pragma unroll
        for (int j = 0; j < 8; j++) {
            const int col = j * 8 + tg * 2;
            const float b0 = __ldg(bias + col);
            const float b1 = __ldg(bias + col + 1);
            stage[(wrow + g) * 66 + col]         = acc[j][0] + b0;
            stage[(wrow + g) * 66 + col + 1]     = acc[j][1] + b1;
            stage[(wrow + g + 8) * 66 + col]     = acc[j][2] + b0;
            stage[(wrow + g + 8) * 66 + col + 1] = acc[j][3] + b1;
        }
        __syncthreads();
        const int bb   = row0 >> 11;
        const int srow = row0 & 2047;
        const int vc = tid >> 2;
        #pragma unroll
        for (int i = 0; i < 16; i++) {
            int sp = (tid & 3) + i * 4;
            int s0 = sp * 2;
            uint32_t h, l;
            fsplit2(stage[s0 * 66 + vc], stage[(s0 + 1) * 66 + vc], h, l);
            size_t off = ((size_t)bb * DK + vc) * SEQ + srow + s0;
            *(uint32_t*)&g_vth[off] = h;
            *(uint32_t*)&g_vtl[off] = l;
        }
    }
}

// ============================ mma.sync flash attention ============================
// grid (32, 4): 64 queries/CTA, 8 warps (warps 0-3 even key tiles, 4-7 odd).
// cp.async double-buffered staging; ldmatrix fragment loads.
#define ASTR 72
static const int TILE_E = 64 * ASTR;                 // 4608 elems per tile
static const int ABUF_E = 8 * TILE_E;                // one iter-buffer (2 tiles x 4 arrays)
static const int AT_BYTES = 2 * ABUF_E * 2;          // 147456 B

__device__ __forceinline__ void attn_stage(int b, int it, int buf, uint32_t sb, int tid)
{
    const uint32_t bufb = (uint32_t)(buf * ABUF_E * 2);
    #pragma unroll
    for (int t = 0; t < 2; t++) {
        const int kb = it * 2 + t;
        #pragma unroll
        for (int u = 0; u < 2; u++) {
            int idx = tid + u * 256;
            int r = idx >> 3, cq = idx & 7;
            size_t koff = ((size_t)b * SEQ + kb * 64 + r) * DK + cq * 8;
            size_t voff = ((size_t)b * DK + r) * SEQ + kb * 64 + cq * 8;
            uint32_t dst = sb + bufb + (uint32_t)((t * TILE_E + r * ASTR + cq * 8) * 2);
            CP_ASYNC16(dst,                    g_kh + koff);
            CP_ASYNC16(dst + 2 * TILE_E * 2,   g_kl + koff);
            CP_ASYNC16(dst + 4 * TILE_E * 2,   g_vth + voff);
            CP_ASYNC16(dst + 6 * TILE_E * 2,   g_vtl + voff);
        }
    }
}

__global__ __launch_bounds__(256) void attn_mma(float* __restrict__ out)
{
    extern __shared__ __nv_bfloat16 asmem[];

    const int b  = blockIdx.y;
    const int q0 = blockIdx.x * 64;
    const int tid = threadIdx.x;
    const int wid = tid >> 5;
    const int lane = tid & 31;
    const int g  = lane >> 2;
    const int tg = lane & 3;
    const int qw = wid & 3;          // query slab
    const int half = wid >> 2;       // key-half
    const int wrow = qw * 16;
    const float scale = 0.125f;

    const uint32_t sb = smem_u32(asmem);
    // ldmatrix lane offset (B-operand pattern, shared by K and V tiles)
    const int brow = (lane & 7) + ((lane >> 4) & 1) * 8;
    const uint32_t lmo = (uint32_t)((brow * ASTR + ((lane >> 3) & 1) * 8) * 2);

    // Q fragments
    const size_t qbase = (size_t)b * SEQ + q0 + wrow;
    uint32_t qh[4][4], ql[4][4];
    #pragma unroll
    for (int ks = 0; ks < 4; ks++) {
        const int c0 = ks * 16 + tg * 2;
        qh[ks][0] = *(const uint32_t*)&g_qh[(qbase + g    ) * DK + c0];
        qh[ks][1] = *(const uint32_t*)&g_qh[(qbase + g + 8) * DK + c0];
        qh[ks][2] = *(const uint32_t*)&g_qh[(qbase + g    ) * DK + c0 + 8];
        qh[ks][3] = *(const uint32_t*)&g_qh[(qbase + g + 8) * DK + c0 + 8];
        ql[ks][0] = *(const uint32_t*)&g_ql[(qbase + g    ) * DK + c0];
        ql[ks][1] = *(const uint32_t*)&g_ql[(qbase + g + 8) * DK + c0];
        ql[ks][2] = *(const uint32_t*)&g_ql[(qbase + g    ) * DK + c0 + 8];
        ql[ks][3] = *(const uint32_t*)&g_ql[(qbase + g + 8) * DK + c0 + 8];
    }

    float m0 = -1e30f, m1 = -1e30f, l0 = 0.0f, l1 = 0.0f;
    float o[8][4];
    #pragma unroll
    for (int j = 0; j < 8; j++)
        #pragma unroll
        for (int q = 0; q < 4; q++) o[j][q] = 0.0f;

    attn_stage(b, 0, 0, sb, tid);
    CP_COMMIT();

    for (int it = 0; it < 16; it++) {
        const int bf = it & 1;
        CP_WAIT0();
        __syncthreads();
        if (it < 15) {
            attn_stage(b, it + 1, bf ^ 1, sb, tid);
            CP_COMMIT();
        }

        // this warp's fragment base addresses within buffer bf
        const uint32_t kh_a = sb + (uint32_t)(bf * ABUF_E * 2) +
                              (uint32_t)(half * TILE_E * 2) + lmo;
        const uint32_t kl_a = kh_a + 2 * TILE_E * 2;
        const uint32_t vh_a = kh_a + 4 * TILE_E * 2;
        const uint32_t vl_a = kh_a + 6 * TILE_E * 2;

        // S = Q K^T (split-bf16, 3 terms)
        float sc[8][4];
        #pragma unroll
        for (int j = 0; j < 8; j++)
            #pragma unroll
            for (int q = 0; q < 4; q++) sc[j][q] = 0.0f;
        #pragma unroll
        for (int ks = 0; ks < 4; ks++) {
            #pragma unroll
            for (int t = 0; t < 4; t++) {
                const uint32_t toff = t * (16 * ASTR * 2) + ks * 32;
                uint32_t bh0, bh1, bh2, bh3, bl0, bl1, bl2, bl3;
                LDSM_X4(bh0, bh1, bh2, bh3, kh_a + toff);
                LDSM_X4(bl0, bl1, bl2, bl3, kl_a + toff);
                mma16816s(sc[2*t],   qh[ks][0], qh[ks][1], qh[ks][2], qh[ks][3], bh0, bh1);
                mma16816s(sc[2*t],   qh[ks][0], qh[ks][1], qh[ks][2], qh[ks][3], bl0, bl1);
                mma16816s(sc[2*t],   ql[ks][0], ql[ks][1], ql[ks][2], ql[ks][3], bh0, bh1);
                mma16816s(sc[2*t+1], qh[ks][0], qh[ks][1], qh[ks][2], qh[ks][3], bh2, bh3);
                mma16816s(sc[2*t+1], qh[ks][0], qh[ks][1], qh[ks][2], qh[ks][3], bl2, bl3);
                mma16816s(sc[2*t+1], ql[ks][0], ql[ks][1], ql[ks][2], ql[ks][3], bh2, bh3);
            }
        }

        // online softmax (rows g and g+8; reduce across 4 tg lanes)
        float mx0 = -1e30f, mx1 = -1e30f;
        #pragma unroll
        for (int j = 0; j < 8; j++) {
            mx0 = fmaxf(mx0, fmaxf(sc[j][0], sc[j][1]));
            mx1 = fmaxf(mx1, fmaxf(sc[j][2], sc[j][3]));
        }
        #pragma unroll
        for (int off = 1; off <= 2; off <<= 1) {
            mx0 = fmaxf(mx0, __shfl_xor_sync(0xffffffffu, mx0, off));
            mx1 = fmaxf(mx1, __shfl_xor_sync(0xffffffffu, mx1, off));
        }
        mx0 *= scale; mx1 *= scale;
        const float mn0 = fmaxf(m0, mx0);
        const float mn1 = fmaxf(m1, mx1);
        const float corr0 = __expf(m0 - mn0);
        const float corr1 = __expf(m1 - mn1);

        float ps0 = 0.0f, ps1 = 0.0f;
        uint32_t ph[8][2], pl[8][2];
        #pragma unroll
        for (int j = 0; j < 8; j++) {
            float p0 = __expf(sc[j][0] * scale - mn0);
            float p1 = __expf(sc[j][1] * scale - mn0);
            float p2 = __expf(sc[j][2] * scale - mn1);
            float p3 = __expf(sc[j][3] * scale - mn1);
            ps0 += p0 + p1; ps1 += p2 + p3;
            fsplit2(p0, p1, ph[j][0], pl[j][0]);
            fsplit2(p2, p3, ph[j][1], pl[j][1]);
        }
        #pragma unroll
        for (int off = 1; off <= 2; off <<= 1) {
            ps0 += __shfl_xor_sync(0xffffffffu, ps0, off);
            ps1 += __shfl_xor_sync(0xffffffffu, ps1, off);
        }
        l0 = l0 * corr0 + ps0;
        l1 = l1 * corr1 + ps1;
        m0 = mn0; m1 = mn1;
        #pragma unroll
        for (int j = 0; j < 8; j++) {
            o[j][0] *= corr0; o[j][1] *= corr0;
            o[j][2] *= corr1; o[j][3] *= corr1;
        }

        // O += P V (split-bf16, 3 terms)
        #pragma unroll
        for (int ks = 0; ks < 4; ks++) {
            const uint32_t pa0 = ph[2*ks][0], pa1 = ph[2*ks][1];
            const uint32_t pa2 = ph[2*ks+1][0], pa3 = ph[2*ks+1][1];
            const uint32_t pb0 = pl[2*ks][0], pb1 = pl[2*ks][1];
            const uint32_t pb2 = pl[2*ks+1][0], pb3 = pl[2*ks+1][1];
            #pragma unroll
            for (int t = 0; t < 4; t++) {
                const uint32_t toff = t * (16 * ASTR * 2) + ks * 32;
                uint32_t bh0, bh1, bh2, bh3, bl0, bl1, bl2, bl3;
                LDSM_X4(bh0, bh1, bh2, bh3, vh_a + toff);
                LDSM_X4(bl0, bl1, bl2, bl3, vl_a + toff);
                mma16816s(o[2*t],   pa0, pa1, pa2, pa3, bh0, bh1);
                mma16816s(o[2*t],   pa0, pa1, pa2, pa3, bl0, bl1);
                mma16816s(o[2*t],   pb0, pb1, pb2, pb3, bh0, bh1);
                mma16816s(o[2*t+1], pa0, pa1, pa2, pa3, bh2, bh3);
                mma16816s(o[2*t+1], pa0, pa1, pa2, pa3, bl2, bl3);
                mma16816s(o[2*t+1], pb0, pb1, pb2, pb3, bh2, bh3);
            }
        }
    }

    // ---------------- split-softmax merge (halves 1 -> 0) ----------------
    __syncthreads();
    float* buf = (float*)asmem;     // reuse: [4][32][36]
    if (half) {
        float* p = buf + ((size_t)qw * 32 + lane) * 36;
        #pragma unroll
        for (int j = 0; j < 8; j++) {
            p[j * 4 + 0] = o[j][0]; p[j * 4 + 1] = o[j][1];
            p[j * 4 + 2] = o[j][2]; p[j * 4 + 3] = o[j][3];
        }
        p[32] = m0; p[33] = m1; p[34] = l0; p[35] = l1;
    }
    __syncthreads();
    if (!half) {
        const float* p = buf + ((size_t)qw * 32 + lane) * 36;
        const float mB0 = p[32], mB1 = p[33], lB0 = p[34], lB1 = p[35];
        const float mn0 = fmaxf(m0, mB0), mn1 = fmaxf(m1, mB1);
        const float cA0 = __expf(m0 - mn0), cB0 = __expf(mB0 - mn0);
        const float cA1 = __expf(m1 - mn1), cB1 = __expf(mB1 - mn1);
        const float inv0 = 1.0f / (l0 * cA0 + lB0 * cB0);
        const float inv1 = 1.0f / (l1 * cA1 + lB1 * cB1);
        #pragma unroll
        for (int j = 0; j < 8; j++) {
            const int col = j * 8 + tg * 2;
            size_t r0 = ((size_t)b * SEQ + q0 + wrow + g    ) * DK + col;
            size_t r1 = ((size_t)b * SEQ + q0 + wrow + g + 8) * DK + col;
            float o0 = (o[j][0] * cA0 + p[j * 4 + 0] * cB0) * inv0;
            float o1 = (o[j][1] * cA0 + p[j * 4 + 1] * cB0) * inv0;
            float o2 = (o[j][2] * cA1 + p[j * 4 + 2] * cB1) * inv1;
            float o3 = (o[j][3] * cA1 + p[j * 4 + 3] * cB1) * inv1;
            *(float2*)(out + r0) = make_float2(o0, o1);
            *(float2*)(out + r1) = make_float2(o2, o3);
        }
    }
}

// ============================ launch ============================
extern "C" void kernel_launch(void* const* d_in, const int* in_sizes, int n_in,
                              void* d_out, int out_size)
{
    const float* query = (const float*)d_in[0];
    const float* key   = (const float*)d_in[1];
    const float* value = (const float*)d_in[2];
    const float* Wq    = (const float*)d_in[3];
    const float* bq    = (const float*)d_in[4];
    const float* Wk    = (const float*)d_in[5];
    const float* bk    = (const float*)d_in[6];
    const float* Wv    = (const float*)d_in[7];
    const float* bv    = (const float*)d_in[8];
    float* out = (float*)d_out;

    const int proj_smem = PS_ELEMS * (int)sizeof(__nv_bfloat16);  // 55296
    static bool attr_set = false;
    if (!attr_set) {
        cudaFuncSetAttribute(proj_mma,
                             cudaFuncAttributeMaxDynamicSharedMemorySize, proj_smem);
        cudaFuncSetAttribute(attn_mma,
                             cudaFuncAttributeMaxDynamicSharedMemorySize, AT_BYTES);
        attr_set = true;
    }

    prep_w<<<dim3(3, 16), 256>>>(Wq, Wk, Wv);
    proj_mma<<<dim3(64, 3), 256, proj_smem>>>(query, key, value, bq, bk, bv);
    attn_mma<<<dim3(SEQ / 64, BATCH), 256, AT_BYTES>>>(out);
}